// round 3
// baseline (speedup 1.0000x reference)
#include <cuda_runtime.h>

#define NN 100000
#define DEG 8
#define HD 128
#define H3 384

typedef unsigned long long u64;

__device__ __forceinline__ u64 pk2(float lo, float hi){u64 r;asm("mov.b64 %0,{%1,%2};":"=l"(r):"f"(lo),"f"(hi));return r;}
__device__ __forceinline__ u64 bc2(float a){u64 r;asm("mov.b64 %0,{%1,%1};":"=l"(r):"f"(a));return r;}
__device__ __forceinline__ void upk2(u64 v,float&lo,float&hi){asm("mov.b64 {%0,%1},%2;":"=f"(lo),"=f"(hi):"l"(v));}
__device__ __forceinline__ u64 fma2(u64 a,u64 b,u64 c){u64 d;asm("fma.rn.f32x2 %0,%1,%2,%3;":"=l"(d):"l"(a),"l"(b),"l"(c));return d;}

__device__ __forceinline__ float sigf(float x){return __fdividef(1.0f,1.0f+__expf(-x));}
__device__ __forceinline__ float tanhf_(float x){return 2.0f*sigf(2.0f*x)-1.0f;}
__device__ __forceinline__ float g2(const float2&v,int k){return k==0?v.x:v.y;}
__device__ __forceinline__ float g4(const float4&v,int k){return k==0?v.x:(k==1?v.y:(k==2?v.z:v.w));}

// ---------------- Kernel 1: forget path -> c_aggr (scratch in c half of d_out)
// 64 nodes/CTA, 256 thr; thread tile 8 nodes x 4 feats. smem: h[64][128]+U_f[128][128]=96KB.
__global__ __launch_bounds__(256,2)
void k_forget(const float* __restrict__ nh,const float* __restrict__ nc,
              const float* __restrict__ f_in,const float* __restrict__ U_f,
              const float* __restrict__ b_f,float* __restrict__ c_aggr)
{
    extern __shared__ float sm[];
    float* h_s=sm;            // [64][128]
    float* u_s=sm+64*HD;      // [128][128]
    const int tid=threadIdx.x, node0=blockIdx.x*64;
    const int fg=tid&31, ng=tid>>5, f0=fg*4;

    float cacc[8][4];
#pragma unroll
    for(int i=0;i<8;i++){cacc[i][0]=cacc[i][1]=cacc[i][2]=cacc[i][3]=0.f;}

    for(int d=0;d<DEG;d++){
        __syncthreads();
#pragma unroll
        for(int r=0;r<8;r++){
            int idx=tid+r*256, n=idx>>5, k4=idx&31, gn=node0+n;
            float4 v=make_float4(0.f,0.f,0.f,0.f);
            if(gn<NN) v=*reinterpret_cast<const float4*>(nh+((size_t)gn*DEG+d)*HD+k4*4);
            *reinterpret_cast<float4*>(h_s+n*HD+k4*4)=v;
        }
        {
            const float4* ug=reinterpret_cast<const float4*>(U_f+(size_t)d*HD*HD);
            float4* us=reinterpret_cast<float4*>(u_s);
#pragma unroll
            for(int r=0;r<16;r++) us[tid+r*256]=ug[tid+r*256];
        }
        __syncthreads();

        u64 fp[8][2];
        {
            float4 bf=*reinterpret_cast<const float4*>(b_f+d*HD+f0);
            u64 lo=pk2(bf.x,bf.y),hi=pk2(bf.z,bf.w);
#pragma unroll
            for(int i=0;i<8;i++){fp[i][0]=lo;fp[i][1]=hi;}
        }
#pragma unroll 1
        for(int k=0;k<HD;k+=2){
            float2 a2[8];
#pragma unroll
            for(int i=0;i<8;i++) a2[i]=*reinterpret_cast<const float2*>(h_s+(ng*8+i)*HD+k);
#pragma unroll
            for(int kk=0;kk<2;kk++){
                float4 b4=*reinterpret_cast<const float4*>(u_s+(k+kk)*HD+f0);
                u64 bl=pk2(b4.x,b4.y),bh=pk2(b4.z,b4.w);
#pragma unroll
                for(int i=0;i<8;i++){
                    u64 a=bc2(g2(a2[i],kk));
                    fp[i][0]=fma2(a,bl,fp[i][0]);
                    fp[i][1]=fma2(a,bh,fp[i][1]);
                }
            }
        }
#pragma unroll
        for(int i=0;i<8;i++){
            int gn=node0+ng*8+i;
            if(gn<NN){
                float4 fi=*reinterpret_cast<const float4*>(f_in+(size_t)gn*HD+f0);
                float4 cv=*reinterpret_cast<const float4*>(nc+((size_t)gn*DEG+d)*HD+f0);
                float p0,p1,p2,p3; upk2(fp[i][0],p0,p1); upk2(fp[i][1],p2,p3);
                cacc[i][0]+=sigf(p0+fi.x)*cv.x;
                cacc[i][1]+=sigf(p1+fi.y)*cv.y;
                cacc[i][2]+=sigf(p2+fi.z)*cv.z;
                cacc[i][3]+=sigf(p3+fi.w)*cv.w;
            }
        }
    }
#pragma unroll
    for(int i=0;i<8;i++){
        int gn=node0+ng*8+i;
        if(gn<NN)
            *reinterpret_cast<float4*>(c_aggr+(size_t)gn*HD+f0)=
                make_float4(cacc[i][0],cacc[i][1],cacc[i][2],cacc[i][3]);
    }
}

// ---------------- Kernel 2: iou GEMM [N,1024]x[1024,384] + finalize h,c.
// 32 nodes/CTA (3125 blocks exact), 256 thr; thread tile 4 nodes x 12 feats.
// smem: A[32][128] (16KB) + B[32][384] (48KB, reused as iou staging).
__global__ __launch_bounds__(256,2)
void k_iou(const float* __restrict__ nh,const float* __restrict__ iou_in,
           const float* __restrict__ U_a,const float* __restrict__ b_a,
           float* __restrict__ h_out,float* __restrict__ c_io)
{
    extern __shared__ float sm[];
    float* a_s=sm;            // [32][128]
    float* b_s=sm+32*HD;      // [32][384]
    const int tid=threadIdx.x, node0=blockIdx.x*32;
    const int fg=tid&31, ng=tid>>5, f0=fg*12;

    u64 acc[4][6];
#pragma unroll
    for(int i=0;i<4;i++)
#pragma unroll
        for(int j=0;j<6;j++) acc[i][j]=0ull;

    for(int d=0;d<DEG;d++){
        __syncthreads();
#pragma unroll
        for(int r=0;r<4;r++){
            int idx=tid+r*256, n=idx>>5, k4=idx&31;
            *reinterpret_cast<float4*>(a_s+n*HD+k4*4)=
                *reinterpret_cast<const float4*>(nh+((size_t)(node0+n)*DEG+d)*HD+k4*4);
        }
        for(int kb=0;kb<4;kb++){
            __syncthreads();
#pragma unroll
            for(int r=0;r<12;r++){
                int idx=tid+r*256, kk=idx/96, fq=idx%96;
                *reinterpret_cast<float4*>(b_s+kk*H3+fq*4)=
                    *reinterpret_cast<const float4*>(U_a+((size_t)(d*HD+kb*32+kk))*H3+fq*4);
            }
            __syncthreads();
#pragma unroll 1
            for(int k=0;k<32;k+=4){
                float4 a4[4];
#pragma unroll
                for(int i=0;i<4;i++)
                    a4[i]=*reinterpret_cast<const float4*>(a_s+(ng*4+i)*HD+kb*32+k);
#pragma unroll
                for(int kk=0;kk<4;kk++){
                    const float* br=b_s+(k+kk)*H3+f0;
                    float4 b0=*reinterpret_cast<const float4*>(br);
                    float4 b1=*reinterpret_cast<const float4*>(br+4);
                    float4 b2=*reinterpret_cast<const float4*>(br+8);
                    u64 p0=pk2(b0.x,b0.y),p1=pk2(b0.z,b0.w);
                    u64 p2=pk2(b1.x,b1.y),p3=pk2(b1.z,b1.w);
                    u64 p4=pk2(b2.x,b2.y),p5=pk2(b2.z,b2.w);
#pragma unroll
                    for(int i=0;i<4;i++){
                        u64 a=bc2(g4(a4[i],kk));
                        acc[i][0]=fma2(a,p0,acc[i][0]);
                        acc[i][1]=fma2(a,p1,acc[i][1]);
                        acc[i][2]=fma2(a,p2,acc[i][2]);
                        acc[i][3]=fma2(a,p3,acc[i][3]);
                        acc[i][4]=fma2(a,p4,acc[i][4]);
                        acc[i][5]=fma2(a,p5,acc[i][5]);
                    }
                }
            }
        }
    }

    __syncthreads();
    {   // stage iou_aggr + b_aggr into b_s so i/o/u can be regrouped per node
        float4 a0=*reinterpret_cast<const float4*>(b_a+f0);
        float4 a1=*reinterpret_cast<const float4*>(b_a+f0+4);
        float4 a2=*reinterpret_cast<const float4*>(b_a+f0+8);
#pragma unroll
        for(int i=0;i<4;i++){
            float v[12];
            upk2(acc[i][0],v[0],v[1]); upk2(acc[i][1],v[2],v[3]);
            upk2(acc[i][2],v[4],v[5]); upk2(acc[i][3],v[6],v[7]);
            upk2(acc[i][4],v[8],v[9]); upk2(acc[i][5],v[10],v[11]);
            v[0]+=a0.x;v[1]+=a0.y;v[2]+=a0.z;v[3]+=a0.w;
            v[4]+=a1.x;v[5]+=a1.y;v[6]+=a1.z;v[7]+=a1.w;
            v[8]+=a2.x;v[9]+=a2.y;v[10]+=a2.z;v[11]+=a2.w;
            float* row=b_s+(ng*4+i)*H3+f0;
            *reinterpret_cast<float4*>(row)  =make_float4(v[0],v[1],v[2],v[3]);
            *reinterpret_cast<float4*>(row+4)=make_float4(v[4],v[5],v[6],v[7]);
            *reinterpret_cast<float4*>(row+8)=make_float4(v[8],v[9],v[10],v[11]);
        }
    }
    __syncthreads();
    {   // finalize: 1 node x 16 feats per thread
        const int nn=tid>>3, fb=(tid&7)*16, gn=node0+nn;
        const float* ios=b_s+nn*H3;
        const float* iin=iou_in+(size_t)gn*H3;
#pragma unroll
        for(int j=0;j<16;j+=4){
            int f=fb+j;
            float4 vi=*reinterpret_cast<const float4*>(ios+f);
            float4 vo=*reinterpret_cast<const float4*>(ios+f+128);
            float4 vu=*reinterpret_cast<const float4*>(ios+f+256);
            float4 ii=*reinterpret_cast<const float4*>(iin+f);
            float4 io=*reinterpret_cast<const float4*>(iin+f+128);
            float4 iu=*reinterpret_cast<const float4*>(iin+f+256);
            float4 ca=*reinterpret_cast<const float4*>(c_io+(size_t)gn*HD+f);
            float4 cR,hR;
            cR.x=sigf(vi.x+ii.x)*tanhf_(vu.x+iu.x)+ca.x;
            cR.y=sigf(vi.y+ii.y)*tanhf_(vu.y+iu.y)+ca.y;
            cR.z=sigf(vi.z+ii.z)*tanhf_(vu.z+iu.z)+ca.z;
            cR.w=sigf(vi.w+ii.w)*tanhf_(vu.w+iu.w)+ca.w;
            hR.x=sigf(vo.x+io.x)*tanhf_(cR.x);
            hR.y=sigf(vo.y+io.y)*tanhf_(cR.y);
            hR.z=sigf(vo.z+io.z)*tanhf_(cR.z);
            hR.w=sigf(vo.w+io.w)*tanhf_(cR.w);
            *reinterpret_cast<float4*>(h_out+(size_t)gn*HD+f)=hR;
            *reinterpret_cast<float4*>(c_io +(size_t)gn*HD+f)=cR;
        }
    }
}

extern "C" void kernel_launch(void* const* d_in, const int* in_sizes, int n_in,
                              void* d_out, int out_size)
{
    const float* nh    =(const float*)d_in[0];
    const float* nc    =(const float*)d_in[1];
    const float* f_in  =(const float*)d_in[2];
    const float* iou_in=(const float*)d_in[3];
    const float* U_f   =(const float*)d_in[4];
    const float* b_f   =(const float*)d_in[5];
    const float* U_a   =(const float*)d_in[6];
    const float* b_a   =(const float*)d_in[7];

    float* h_out=(float*)d_out;
    float* c_out=h_out+(size_t)NN*HD;

    const int smem1=(64*HD+HD*HD)*(int)sizeof(float);  // 96 KB
    const int smem2=(32*HD+32*H3)*(int)sizeof(float);  // 64 KB
    static bool attr_done=false;
    if(!attr_done){
        cudaFuncSetAttribute(k_forget,cudaFuncAttributeMaxDynamicSharedMemorySize,smem1);
        cudaFuncSetAttribute(k_iou,   cudaFuncAttributeMaxDynamicSharedMemorySize,smem2);
        attr_done=true;
    }

    k_forget<<<(NN+63)/64,256,smem1>>>(nh,nc,f_in,U_f,b_f,c_out);
    k_iou<<<NN/32,256,smem2>>>(nh,iou_in,U_a,b_a,h_out,c_out);
}

// round 10
// speedup vs baseline: 1.8337x; 1.8337x over previous
#include <cuda_runtime.h>

#define NN 100000
#define DEG 8
#define HD 128
#define H3 384
#define MTILE 64
#define NCTA ((NN + MTILE - 1) / MTILE)

typedef unsigned int u32;

// smem float-offset layout
#define AS_STRIDE 132
#define BS_STRIDE 520
#define A0F 0
#define A1F (64 * AS_STRIDE)
#define B0F (2 * 64 * AS_STRIDE)
#define B1F (B0F + 32 * BS_STRIDE)
#define TOTF (B1F + 32 * BS_STRIDE)          // 50176 floats = 200704 B
#define IOUS_STRIDE 392
#define CS_F (64 * IOUS_STRIDE)              // cacc stage at 25088 floats
#define SMEMB (TOTF * 4)

__device__ __forceinline__ u32 s2u(const void* p) {
    u32 a; asm("{ .reg .u64 t; cvta.to.shared.u64 t, %1; cvt.u32.u64 %0, t; }" : "=r"(a) : "l"(p));
    return a;
}
__device__ __forceinline__ float sigf(float x) { return __fdividef(1.0f, 1.0f + __expf(-x)); }
__device__ __forceinline__ float tanhf_(float x) { return 2.0f * sigf(2.0f * x) - 1.0f; }
__device__ __forceinline__ u32 f2tf(float x) {
    u32 r; asm("cvt.rna.tf32.f32 %0, %1;" : "=r"(r) : "f"(x)); return r;
}
__device__ __forceinline__ void cpa(u32 s, const float* g) {
    asm volatile("cp.async.cg.shared.global [%0], [%1], 16;" :: "r"(s), "l"(g) : "memory");
}
__device__ __forceinline__ void sts_zero(u32 s) {
    asm volatile("st.shared.v4.b32 [%0], {%1,%1,%1,%1};" :: "r"(s), "r"(0u) : "memory");
}

#define MMA(C, A, B0, B1) \
    asm volatile("mma.sync.aligned.m16n8k8.row.col.f32.tf32.tf32.f32 " \
        "{%0,%1,%2,%3},{%4,%5,%6,%7},{%8,%9},{%0,%1,%2,%3};" \
        : "+f"((C)[0]), "+f"((C)[1]), "+f"((C)[2]), "+f"((C)[3]) \
        : "r"((A)[0]), "r"((A)[1]), "r"((A)[2]), "r"((A)[3]), "r"(B0), "r"(B1))

__global__ __launch_bounds__(256, 1)
void k_hmma(const float* __restrict__ nh, const float* __restrict__ nc,
            const float* __restrict__ f_in, const float* __restrict__ iou_in,
            const float* __restrict__ U_f, const float* __restrict__ b_f,
            const float* __restrict__ U_a, const float* __restrict__ b_a,
            float* __restrict__ h_out, float* __restrict__ c_out)
{
    extern __shared__ float sm[];
    const u32 sb = s2u(sm);
    const int tid = threadIdx.x;
    const int w = tid >> 5, lane = tid & 31;
    const int l4 = lane >> 2, lq = lane & 3;
    const int node0 = blockIdx.x * MTILE;

    float accI[4][6][4];     // iou: cols 48w .. 48w+47, persistent over d
    float accF[4][2][4];     // f:   cols 16w .. 16w+15, reset each d
    float cacc[4][2][4];     // c_aggr accumulator (same layout as accF)
#pragma unroll
    for (int mt = 0; mt < 4; mt++) {
#pragma unroll
        for (int nt = 0; nt < 6; nt++)
#pragma unroll
            for (int c = 0; c < 4; c++) accI[mt][nt][c] = 0.0f;
#pragma unroll
        for (int nt = 0; nt < 2; nt++)
#pragma unroll
            for (int c = 0; c < 4; c++) cacc[mt][nt][c] = 0.0f;
    }

    // ---- load issuer for step s (d = s>>2, chunk = s&3) ----
    auto issue_loads = [&](int s) {
        const int d = s >> 2, ch = s & 3;
        const u32 bbase = sb + ((s & 1) ? B1F : B0F) * 4;
        if (ch == 0) {                       // A tile [64 rows][128 k]
            const u32 abase = sb + ((d & 1) ? A1F : A0F) * 4;
#pragma unroll
            for (int r = 0; r < 8; r++) {
                int idx = tid + r * 256, row = idx >> 5, q = idx & 31;
                u32 dst = abase + row * (AS_STRIDE * 4) + q * 16;
                if (node0 + row < NN)
                    cpa(dst, nh + ((size_t)(node0 + row) * DEG + d) * HD + q * 4);
                else sts_zero(dst);
            }
        }
        // B chunk [32 k][512 n] = [U_aggr rows | U_f rows]
#pragma unroll
        for (int r = 0; r < 16; r++) {
            int idx = tid + r * 256, kk = idx >> 7, q = idx & 127;
            u32 dst = bbase + kk * (BS_STRIDE * 4) + q * 16;
            const float* src = (q < 96)
                ? U_a + (size_t)(d * HD + ch * 32 + kk) * H3 + q * 4
                : U_f + (size_t)d * HD * HD + (size_t)(ch * 32 + kk) * HD + (q - 96) * 4;
            cpa(dst, src);
        }
        asm volatile("cp.async.commit_group;" ::: "memory");
    };

    issue_loads(0);

    for (int step = 0; step < 32; step++) {
        const int d = step >> 2, ch = step & 3;
        const float* As = sm + ((d & 1) ? A1F : A0F);
        const float* Bs = sm + ((step & 1) ? B1F : B0F);

        asm volatile("cp.async.wait_group 0;" ::: "memory");
        __syncthreads();
        if (step < 31) issue_loads(step + 1);

        if (ch == 0) {
#pragma unroll
            for (int mt = 0; mt < 4; mt++)
#pragma unroll
                for (int nt = 0; nt < 2; nt++)
#pragma unroll
                    for (int c = 0; c < 4; c++) accF[mt][nt][c] = 0.0f;
        }

        // ---- compute: 4 k8-steps over this 32-k chunk ----
#pragma unroll
        for (int ks = 0; ks < 4; ks++) {
            const int ka = ch * 32 + ks * 8 + lq;   // A column within the 128-wide d tile (FIX)
            const int kb = ks * 8 + lq;             // B row within the 32-row chunk
            u32 a[4][4];
#pragma unroll
            for (int mt = 0; mt < 4; mt++) {
                a[mt][0] = f2tf(As[(mt * 16 + l4) * AS_STRIDE + ka]);
                a[mt][1] = f2tf(As[(mt * 16 + l4 + 8) * AS_STRIDE + ka]);
                a[mt][2] = f2tf(As[(mt * 16 + l4) * AS_STRIDE + ka + 4]);
                a[mt][3] = f2tf(As[(mt * 16 + l4 + 8) * AS_STRIDE + ka + 4]);
            }
#pragma unroll
            for (int nt = 0; nt < 8; nt++) {
                const int ncol = (nt < 6) ? (48 * w + nt * 8)
                                          : (384 + 16 * w + (nt - 6) * 8);
                u32 b0 = f2tf(Bs[kb * BS_STRIDE + ncol + l4]);
                u32 b1 = f2tf(Bs[(kb + 4) * BS_STRIDE + ncol + l4]);
                if (nt < 6) {
#pragma unroll
                    for (int mt = 0; mt < 4; mt++) MMA(accI[mt][nt], a[mt], b0, b1);
                } else {
#pragma unroll
                    for (int mt = 0; mt < 4; mt++) MMA(accF[mt][nt - 6], a[mt], b0, b1);
                }
            }
        }

        // ---- per-d forget epilogue: cacc += sigmoid(f_pre + b_f + f_in) * c ----
        if (ch == 3) {
#pragma unroll
            for (int mt = 0; mt < 4; mt++)
#pragma unroll
                for (int h = 0; h < 2; h++) {
                    const int row = mt * 16 + l4 + 8 * h;
                    const int gn = node0 + row;
                    if (gn < NN) {
#pragma unroll
                        for (int nt = 0; nt < 2; nt++) {
                            const int col = 16 * w + nt * 8 + 2 * lq;
                            float2 bf = __ldg((const float2*)(b_f + d * HD + col));
                            float2 fi = __ldg((const float2*)(f_in + (size_t)gn * HD + col));
                            float2 cv = __ldg((const float2*)(nc + ((size_t)gn * DEG + d) * HD + col));
                            cacc[mt][nt][2 * h]     += sigf(accF[mt][nt][2 * h]     + bf.x + fi.x) * cv.x;
                            cacc[mt][nt][2 * h + 1] += sigf(accF[mt][nt][2 * h + 1] + bf.y + fi.y) * cv.y;
                        }
                    }
                }
        }
    }

    // ---- stage iou + cacc through smem for coalesced i/o/u regrouping ----
    __syncthreads();
    {
        float* S1 = sm;                 // [64][392] iou
        float* S2 = sm + CS_F;          // [64][132] cacc
#pragma unroll
        for (int mt = 0; mt < 4; mt++)
#pragma unroll
            for (int h = 0; h < 2; h++) {
                const int row = mt * 16 + l4 + 8 * h;
#pragma unroll
                for (int nt = 0; nt < 6; nt++) {
                    const int col = 48 * w + nt * 8 + 2 * lq;
                    *(float2*)&S1[row * IOUS_STRIDE + col] =
                        make_float2(accI[mt][nt][2 * h], accI[mt][nt][2 * h + 1]);
                }
#pragma unroll
                for (int nt = 0; nt < 2; nt++) {
                    const int col = 16 * w + nt * 8 + 2 * lq;
                    *(float2*)&S2[row * AS_STRIDE + col] =
                        make_float2(cacc[mt][nt][2 * h], cacc[mt][nt][2 * h + 1]);
                }
            }
    }
    __syncthreads();

    // ---- finalize: 1 row x 32 cols per thread, fully coalesced gmem ----
    {
        const float* S1 = sm;
        const float* S2 = sm + CS_F;
        const int r = tid >> 2, cq = (tid & 3) * 32;
        const int gn = node0 + r;
        if (gn < NN) {
            const float* iin = iou_in + (size_t)gn * H3;
#pragma unroll
            for (int j = 0; j < 32; j += 4) {
                const int c = cq + j;
                float4 vi = *(const float4*)&S1[r * IOUS_STRIDE + c];
                float4 vo = *(const float4*)&S1[r * IOUS_STRIDE + 128 + c];
                float4 vu = *(const float4*)&S1[r * IOUS_STRIDE + 256 + c];
                float4 ca = *(const float4*)&S2[r * AS_STRIDE + c];
                float4 ii = __ldg((const float4*)(iin + c));
                float4 io = __ldg((const float4*)(iin + 128 + c));
                float4 iu = __ldg((const float4*)(iin + 256 + c));
                float4 bi = __ldg((const float4*)(b_a + c));
                float4 bo = __ldg((const float4*)(b_a + 128 + c));
                float4 bu = __ldg((const float4*)(b_a + 256 + c));
                float4 cR, hR;
                cR.x = sigf(vi.x + bi.x + ii.x) * tanhf_(vu.x + bu.x + iu.x) + ca.x;
                cR.y = sigf(vi.y + bi.y + ii.y) * tanhf_(vu.y + bu.y + iu.y) + ca.y;
                cR.z = sigf(vi.z + bi.z + ii.z) * tanhf_(vu.z + bu.z + iu.z) + ca.z;
                cR.w = sigf(vi.w + bi.w + ii.w) * tanhf_(vu.w + bu.w + iu.w) + ca.w;
                hR.x = sigf(vo.x + bo.x + io.x) * tanhf_(cR.x);
                hR.y = sigf(vo.y + bo.y + io.y) * tanhf_(cR.y);
                hR.z = sigf(vo.z + bo.z + io.z) * tanhf_(cR.z);
                hR.w = sigf(vo.w + bo.w + io.w) * tanhf_(cR.w);
                *(float4*)(h_out + (size_t)gn * HD + c) = hR;
                *(float4*)(c_out + (size_t)gn * HD + c) = cR;
            }
        }
    }
}

extern "C" void kernel_launch(void* const* d_in, const int* in_sizes, int n_in,
                              void* d_out, int out_size)
{
    const float* nh     = (const float*)d_in[0];
    const float* nc     = (const float*)d_in[1];
    const float* f_in   = (const float*)d_in[2];
    const float* iou_in = (const float*)d_in[3];
    const float* U_f    = (const float*)d_in[4];
    const float* b_f    = (const float*)d_in[5];
    const float* U_a    = (const float*)d_in[6];
    const float* b_a    = (const float*)d_in[7];

    float* h_out = (float*)d_out;
    float* c_out = h_out + (size_t)NN * HD;

    static bool attr_done = false;
    if (!attr_done) {
        cudaFuncSetAttribute(k_hmma, cudaFuncAttributeMaxDynamicSharedMemorySize, SMEMB);
        attr_done = true;
    }

    k_hmma<<<NCTA, 256, SMEMB>>>(nh, nc, f_in, iou_in, U_f, b_f, U_a, b_a, h_out, c_out);
}

// round 12
// speedup vs baseline: 1.9004x; 1.0363x over previous
#include <cuda_runtime.h>

#define NN 100000
#define DEG 8
#define HD 128
#define H3 384
#define MTILE 64
#define NTHR 512
#define NCTA ((NN + MTILE - 1) / MTILE)

typedef unsigned int u32;

// smem float-offset layout
#define AS_STRIDE 132
#define BS_STRIDE 520
#define A0F 0
#define A1F (64 * AS_STRIDE)
#define B0F (2 * 64 * AS_STRIDE)
#define B1F (B0F + 32 * BS_STRIDE)
#define TOTF (B1F + 32 * BS_STRIDE)          // 50176 floats = 200704 B
#define IOUS_STRIDE 392
#define CS_F (64 * IOUS_STRIDE)
#define SMEMB (TOTF * 4)

__device__ __forceinline__ u32 s2u(const void* p) {
    u32 a; asm("{ .reg .u64 t; cvta.to.shared.u64 t, %1; cvt.u32.u64 %0, t; }" : "=r"(a) : "l"(p));
    return a;
}
__device__ __forceinline__ float sigf(float x) { return __fdividef(1.0f, 1.0f + __expf(-x)); }
__device__ __forceinline__ float tanhf_(float x) { return 2.0f * sigf(2.0f * x) - 1.0f; }
__device__ __forceinline__ u32 f2tf(float x) {
    u32 r; asm("cvt.rna.tf32.f32 %0, %1;" : "=r"(r) : "f"(x)); return r;
}
__device__ __forceinline__ void cpa(u32 s, const float* g) {
    asm volatile("cp.async.cg.shared.global [%0], [%1], 16;" :: "r"(s), "l"(g) : "memory");
}
__device__ __forceinline__ void sts_zero(u32 s) {
    asm volatile("st.shared.v4.b32 [%0], {%1,%1,%1,%1};" :: "r"(s), "r"(0u) : "memory");
}

#define MMA(C, A, B0, B1) \
    asm volatile("mma.sync.aligned.m16n8k8.row.col.f32.tf32.tf32.f32 " \
        "{%0,%1,%2,%3},{%4,%5,%6,%7},{%8,%9},{%0,%1,%2,%3};" \
        : "+f"((C)[0]), "+f"((C)[1]), "+f"((C)[2]), "+f"((C)[3]) \
        : "r"((A)[0]), "r"((A)[1]), "r"((A)[2]), "r"((A)[3]), "r"(B0), "r"(B1))

__global__ __launch_bounds__(NTHR, 1)
void k_hmma(const float* __restrict__ nh, const float* __restrict__ nc,
            const float* __restrict__ f_in, const float* __restrict__ iou_in,
            const float* __restrict__ U_f, const float* __restrict__ b_f,
            const float* __restrict__ U_a, const float* __restrict__ b_a,
            float* __restrict__ h_out, float* __restrict__ c_out)
{
    extern __shared__ float sm[];
    const u32 sb = s2u(sm);
    const int tid = threadIdx.x;
    const int w = tid >> 5, lane = tid & 31;          // 16 warps
    const int l4 = lane >> 2, lq = lane & 3;
    const int node0 = blockIdx.x * MTILE;

    float accI[4][3][4];     // iou: cols 24w .. 24w+23, persistent over d
    float accF[4][4];        // f:   cols 8w .. 8w+7, reset each d
    float cacc[4][4];        // c_aggr accumulator
#pragma unroll
    for (int mt = 0; mt < 4; mt++) {
#pragma unroll
        for (int nt = 0; nt < 3; nt++)
#pragma unroll
            for (int c = 0; c < 4; c++) accI[mt][nt][c] = 0.0f;
#pragma unroll
        for (int c = 0; c < 4; c++) cacc[mt][c] = 0.0f;
    }

    // ---- load issuer for step s (d = s>>2, chunk = s&3) ----
    auto issue_loads = [&](int s) {
        const int d = s >> 2, ch = s & 3;
        const u32 bbase = sb + ((s & 1) ? B1F : B0F) * 4;
        if (ch == 0) {                       // A tile [64 rows][128 k]: 2048 float4
            const u32 abase = sb + ((d & 1) ? A1F : A0F) * 4;
#pragma unroll
            for (int r = 0; r < 4; r++) {
                int idx = tid + r * NTHR, row = idx >> 5, q = idx & 31;
                u32 dst = abase + row * (AS_STRIDE * 4) + q * 16;
                if (node0 + row < NN)
                    cpa(dst, nh + ((size_t)(node0 + row) * DEG + d) * HD + q * 4);
                else sts_zero(dst);
            }
        }
        // B chunk [32 k][512 n] = [U_aggr | U_f]: 4096 float4
#pragma unroll
        for (int r = 0; r < 8; r++) {
            int idx = tid + r * NTHR, kk = idx >> 7, q = idx & 127;
            u32 dst = bbase + kk * (BS_STRIDE * 4) + q * 16;
            const float* src = (q < 96)
                ? U_a + (size_t)(d * HD + ch * 32 + kk) * H3 + q * 4
                : U_f + (size_t)d * HD * HD + (size_t)(ch * 32 + kk) * HD + (q - 96) * 4;
            cpa(dst, src);
        }
        asm volatile("cp.async.commit_group;" ::: "memory");
    };

    issue_loads(0);

    for (int step = 0; step < 32; step++) {
        const int d = step >> 2, ch = step & 3;
        const float* As = sm + ((d & 1) ? A1F : A0F);
        const float* Bs = sm + ((step & 1) ? B1F : B0F);

        asm volatile("cp.async.wait_group 0;" ::: "memory");
        __syncthreads();
        if (step < 31) issue_loads(step + 1);

        if (ch == 0) {
#pragma unroll
            for (int mt = 0; mt < 4; mt++)
#pragma unroll
                for (int c = 0; c < 4; c++) accF[mt][c] = 0.0f;
        }

        // ---- compute: 4 k8-steps over this 32-k chunk ----
#pragma unroll
        for (int ks = 0; ks < 4; ks++) {
            const int ka = ch * 32 + ks * 8 + lq;   // A col within 128-wide d tile
            const int kb = ks * 8 + lq;             // B row within 32-row chunk
            u32 a[4][4];
#pragma unroll
            for (int mt = 0; mt < 4; mt++) {
                a[mt][0] = f2tf(As[(mt * 16 + l4) * AS_STRIDE + ka]);
                a[mt][1] = f2tf(As[(mt * 16 + l4 + 8) * AS_STRIDE + ka]);
                a[mt][2] = f2tf(As[(mt * 16 + l4) * AS_STRIDE + ka + 4]);
                a[mt][3] = f2tf(As[(mt * 16 + l4 + 8) * AS_STRIDE + ka + 4]);
            }
#pragma unroll
            for (int nt = 0; nt < 4; nt++) {
                const int ncol = (nt < 3) ? (24 * w + nt * 8) : (384 + 8 * w);
                u32 b0 = f2tf(Bs[kb * BS_STRIDE + ncol + l4]);
                u32 b1 = f2tf(Bs[(kb + 4) * BS_STRIDE + ncol + l4]);
                if (nt < 3) {
#pragma unroll
                    for (int mt = 0; mt < 4; mt++) MMA(accI[mt][nt], a[mt], b0, b1);
                } else {
#pragma unroll
                    for (int mt = 0; mt < 4; mt++) MMA(accF[mt], a[mt], b0, b1);
                }
            }
        }

        // ---- per-d forget epilogue: cacc += sigmoid(f_pre + b_f + f_in) * c ----
        if (ch == 3) {
#pragma unroll
            for (int mt = 0; mt < 4; mt++)
#pragma unroll
                for (int h = 0; h < 2; h++) {
                    const int row = mt * 16 + l4 + 8 * h;
                    const int gn = node0 + row;
                    if (gn < NN) {
                        const int col = 8 * w + 2 * lq;
                        float2 bf = __ldg((const float2*)(b_f + d * HD + col));
                        float2 fi = __ldg((const float2*)(f_in + (size_t)gn * HD + col));
                        float2 cv = __ldg((const float2*)(nc + ((size_t)gn * DEG + d) * HD + col));
                        cacc[mt][2 * h]     += sigf(accF[mt][2 * h]     + bf.x + fi.x) * cv.x;
                        cacc[mt][2 * h + 1] += sigf(accF[mt][2 * h + 1] + bf.y + fi.y) * cv.y;
                    }
                }
        }
    }

    // ---- stage iou + cacc through smem for coalesced i/o/u regrouping ----
    __syncthreads();
    {
        float* S1 = sm;                 // [64][392] iou
        float* S2 = sm + CS_F;          // [64][132] cacc
#pragma unroll
        for (int mt = 0; mt < 4; mt++)
#pragma unroll
            for (int h = 0; h < 2; h++) {
                const int row = mt * 16 + l4 + 8 * h;
#pragma unroll
                for (int nt = 0; nt < 3; nt++) {
                    const int col = 24 * w + nt * 8 + 2 * lq;
                    *(float2*)&S1[row * IOUS_STRIDE + col] =
                        make_float2(accI[mt][nt][2 * h], accI[mt][nt][2 * h + 1]);
                }
                const int colf = 8 * w + 2 * lq;
                *(float2*)&S2[row * AS_STRIDE + colf] =
                    make_float2(cacc[mt][2 * h], cacc[mt][2 * h + 1]);
            }
    }
    __syncthreads();

    // ---- finalize: 1 row x 16 cols per thread, fully coalesced gmem ----
    {
        const float* S1 = sm;
        const float* S2 = sm + CS_F;
        const int r = tid >> 3, cq = (tid & 7) * 16;
        const int gn = node0 + r;
        if (gn < NN) {
            const float* iin = iou_in + (size_t)gn * H3;
#pragma unroll
            for (int j = 0; j < 16; j += 4) {
                const int c = cq + j;
                float4 vi = *(const float4*)&S1[r * IOUS_STRIDE + c];
                float4 vo = *(const float4*)&S1[r * IOUS_STRIDE + 128 + c];
                float4 vu = *(const float4*)&S1[r * IOUS_STRIDE + 256 + c];
                float4 ca = *(const float4*)&S2[r * AS_STRIDE + c];
                float4 ii = __ldg((const float4*)(iin + c));
                float4 io = __ldg((const float4*)(iin + 128 + c));
                float4 iu = __ldg((const float4*)(iin + 256 + c));
                float4 bi = __ldg((const float4*)(b_a + c));
                float4 bo = __ldg((const float4*)(b_a + 128 + c));
                float4 bu = __ldg((const float4*)(b_a + 256 + c));
                float4 cR, hR;
                cR.x = sigf(vi.x + bi.x + ii.x) * tanhf_(vu.x + bu.x + iu.x) + ca.x;
                cR.y = sigf(vi.y + bi.y + ii.y) * tanhf_(vu.y + bu.y + iu.y) + ca.y;
                cR.z = sigf(vi.z + bi.z + ii.z) * tanhf_(vu.z + bu.z + iu.z) + ca.z;
                cR.w = sigf(vi.w + bi.w + ii.w) * tanhf_(vu.w + bu.w + iu.w) + ca.w;
                hR.x = sigf(vo.x + bo.x + io.x) * tanhf_(cR.x);
                hR.y = sigf(vo.y + bo.y + io.y) * tanhf_(cR.y);
                hR.z = sigf(vo.z + bo.z + io.z) * tanhf_(cR.z);
                hR.w = sigf(vo.w + bo.w + io.w) * tanhf_(cR.w);
                *(float4*)(h_out + (size_t)gn * HD + c) = hR;
                *(float4*)(c_out + (size_t)gn * HD + c) = cR;
            }
        }
    }
}

extern "C" void kernel_launch(void* const* d_in, const int* in_sizes, int n_in,
                              void* d_out, int out_size)
{
    const float* nh     = (const float*)d_in[0];
    const float* nc     = (const float*)d_in[1];
    const float* f_in   = (const float*)d_in[2];
    const float* iou_in = (const float*)d_in[3];
    const float* U_f    = (const float*)d_in[4];
    const float* b_f    = (const float*)d_in[5];
    const float* U_a    = (const float*)d_in[6];
    const float* b_a    = (const float*)d_in[7];

    float* h_out = (float*)d_out;
    float* c_out = h_out + (size_t)NN * HD;

    static bool attr_done = false;
    if (!attr_done) {
        cudaFuncSetAttribute(k_hmma, cudaFuncAttributeMaxDynamicSharedMemorySize, SMEMB);
        attr_done = true;
    }

    k_hmma<<<NCTA, NTHR, SMEMB>>>(nh, nc, f_in, iou_in, U_f, b_f, U_a, b_a, h_out, c_out);
}